// round 13
// baseline (speedup 1.0000x reference)
#include <cuda_runtime.h>
#include <cstdint>

#define BB 32
#define SS 1024
#define DD 64
#define TQ 64
#define TK 64
#define NT 128

#define KS_STRIDE 68
#define VS_STRIDE 72
#define RP_STRIDE 129
#define PT_STRIDE 136

// smem float offsets: K and V both double-buffered raw fp32
#define KS0_OFF 0                             // 64 x 68
#define KS1_OFF (KS0_OFF + 64*KS_STRIDE)      // 4352
#define VS0_OFF (KS1_OFF + 64*KS_STRIDE)      // 8704, 64 x 72
#define VS1_OFF (VS0_OFF + 64*VS_STRIDE)      // 13312
#define RP_OFF  (VS1_OFF + 64*VS_STRIDE)      // 17920
#define SMEM_FLOATS (RP_OFF + 64*RP_STRIDE)   // 26176 floats = 104704 B -> 2 CTAs/SM
#define PT_OFF VS0_OFF                        // ptt aliases V buffers (8704 <= 9216)

__device__ __forceinline__ unsigned f2tf(float f) {
    unsigned u; asm("cvt.rna.tf32.f32 %0, %1;" : "=r"(u) : "f"(f)); return u;
}
__device__ __forceinline__ void mma_tf32(float c[4], const unsigned a[4],
                                         unsigned b0, unsigned b1) {
    asm volatile(
        "mma.sync.aligned.m16n8k8.row.col.f32.tf32.tf32.f32 "
        "{%0,%1,%2,%3}, {%4,%5,%6,%7}, {%8,%9}, {%0,%1,%2,%3};"
        : "+f"(c[0]), "+f"(c[1]), "+f"(c[2]), "+f"(c[3])
        : "r"(a[0]), "r"(a[1]), "r"(a[2]), "r"(a[3]), "r"(b0), "r"(b1));
}
__device__ __forceinline__ void cpa16(unsigned s, const void* g) {
    asm volatile("cp.async.cg.shared.global [%0], [%1], 16;" :: "r"(s), "l"(g));
}
#define CP_COMMIT() asm volatile("cp.async.commit_group;")
#define CP_WAIT(n)  asm volatile("cp.async.wait_group %0;" :: "n"(n))

// pack 16 ints (4 int4) into 16 mask bits
__device__ __forceinline__ unsigned pack16(const int4* m4) {
    unsigned bits = 0;
    #pragma unroll
    for (int l = 0; l < 4; l++) {
        int4 v = m4[l];
        unsigned nib = (unsigned)(v.x != 0) | ((unsigned)(v.y != 0) << 1)
                     | ((unsigned)(v.z != 0) << 2) | ((unsigned)(v.w != 0) << 3);
        bits |= nib << (4 * l);
    }
    return bits;
}

// rp-table GEMM chunk: stores PRE-SCALED values rp'[r][j] = (q[r,:].pt[j,:])*0.125 - 16
template<int NB0, int NBN>
__device__ __forceinline__ void rp_mma_chunk(const unsigned aq[8][4], const float* ptt,
                                             float* rp, int r0, int r1, int u, int g) {
    float c[NBN][4];
    #pragma unroll
    for (int n = 0; n < NBN; n++) { c[n][0]=0.f; c[n][1]=0.f; c[n][2]=0.f; c[n][3]=0.f; }
    #pragma unroll
    for (int s = 0; s < 8; s++) {
        #pragma unroll
        for (int n = 0; n < NBN; n++) {
            int jr = (NB0 + n) * 8 + g;
            unsigned b0 = __float_as_uint(ptt[(8*s + u)     * PT_STRIDE + jr]);
            unsigned b1 = __float_as_uint(ptt[(8*s + u + 4) * PT_STRIDE + jr]);
            mma_tf32(c[n], aq[s], b0, b1);
        }
    }
    #pragma unroll
    for (int n = 0; n < NBN; n++) {
        int col = (NB0 + n) * 8 + 2 * u;
        if (col <= 128) {
            rp[r0*RP_STRIDE + col] = fmaf(c[n][0], 0.125f, -16.f);
            rp[r1*RP_STRIDE + col] = fmaf(c[n][2], 0.125f, -16.f);
        }
        if (col + 1 <= 128) {
            rp[r0*RP_STRIDE + col + 1] = fmaf(c[n][1], 0.125f, -16.f);
            rp[r1*RP_STRIDE + col + 1] = fmaf(c[n][3], 0.125f, -16.f);
        }
    }
}

__global__ void __launch_bounds__(NT, 2)
attn_tc_kernel(const float* __restrict__ q,
               const float* __restrict__ k,
               const float* __restrict__ v,
               const int* __restrict__ mask,
               const float* __restrict__ pt,
               float* __restrict__ out) {
    extern __shared__ float sm[];
    float* rp  = sm + RP_OFF;
    float* ptt = sm + PT_OFF;

    const int tid  = threadIdx.x;
    const int lane = tid & 31;
    const int w    = tid >> 5;
    const int u    = lane & 3;
    const int g    = lane >> 2;
    const int qt   = blockIdx.x, b = blockIdx.y;
    const int qg0  = qt * TQ;
    const int r0   = 16 * w + g;
    const int r1   = r0 + 8;
    const int keysel = (g >> 1) + 4 * (g & 1);   // sigma(g)

    const float4* kg = (const float4*)(k + (size_t)b * SS * DD);
    const float4* vg = (const float4*)(v + (size_t)b * SS * DD);
    const int* mrow0 = mask + (size_t)(b * SS + qg0 + r0) * SS;
    const int* mrow1 = mask + (size_t)(b * SS + qg0 + r1) * SS;

    // ---- issue K0 cp.async FIRST (K region never aliased) -> overlaps rp phase ----
    {
        #pragma unroll
        for (int l = 0; l < 8; l++) {
            int i = tid + l * NT, row = i >> 4, c4 = i & 15;
            unsigned dst = (unsigned)__cvta_generic_to_shared(sm + KS0_OFF + row * KS_STRIDE + c4 * 4);
            cpa16(dst, kg + i);
        }
        CP_COMMIT();
    }

    // ---- phase 0: stage transposed tf32 pos_table (aliases V buffers) ----
    {
        const float4* ptg = (const float4*)pt;
        for (int i = tid; i < 129 * 16; i += NT) {
            int j = i >> 4, c0 = (i & 15) * 4;
            float4 p4 = ptg[i];
            ptt[(c0 + 0) * PT_STRIDE + j] = __uint_as_float(f2tf(p4.x));
            ptt[(c0 + 1) * PT_STRIDE + j] = __uint_as_float(f2tf(p4.y));
            ptt[(c0 + 2) * PT_STRIDE + j] = __uint_as_float(f2tf(p4.z));
            ptt[(c0 + 3) * PT_STRIDE + j] = __uint_as_float(f2tf(p4.w));
        }
        for (int i = tid; i < 64 * 7; i += NT)
            ptt[(i / 7) * PT_STRIDE + 129 + (i % 7)] = 0.f;
    }

    // ---- Q fragments straight from gmem ----
    unsigned aq[8][4];
    {
        const float* q0 = q + (size_t)(b * SS + qg0 + r0) * DD;
        const float* q1 = q + (size_t)(b * SS + qg0 + r1) * DD;
        #pragma unroll
        for (int s = 0; s < 8; s++) {
            aq[s][0] = f2tf(q0[8*s + u]);
            aq[s][1] = f2tf(q1[8*s + u]);
            aq[s][2] = f2tf(q0[8*s + u + 4]);
            aq[s][3] = f2tf(q1[8*s + u + 4]);
        }
    }
    __syncthreads();

    // ---- phase 1: rp table via MMA (pre-scaled: *0.125 - 16) ----
    rp_mma_chunk<0, 9>(aq, ptt, rp, r0, r1, u, g);
    rp_mma_chunk<9, 8>(aq, ptt, rp, r0, r1, u, g);
    __syncthreads();   // ptt (V-buffer alias) dead after this point

    const float rpn0 = rp[r0 * RP_STRIDE + 0],   rpn1 = rp[r1 * RP_STRIDE + 0];
    const float rpp0 = rp[r0 * RP_STRIDE + 128], rpp1 = rp[r1 * RP_STRIDE + 128];

    // ---- issue V0 cp.async (V region now free) ----
    {
        #pragma unroll
        for (int l = 0; l < 8; l++) {
            int i = tid + l * NT, row = i >> 4, c4 = i & 15;
            unsigned dst = (unsigned)__cvta_generic_to_shared(sm + VS0_OFF + row * VS_STRIDE + c4 * 4);
            cpa16(dst, vg + i);
        }
        CP_COMMIT();
    }

    float ps0 = 0.f, ps1 = 0.f;    // per-thread softmax denominators
    float co[8][4];
    #pragma unroll
    for (int j = 0; j < 8; j++) { co[j][0]=0.f; co[j][1]=0.f; co[j][2]=0.f; co[j][3]=0.f; }

    for (int kt = 0; kt < SS / TK; kt++) {
        const int kg0 = kt * TK;
        const int D   = kg0 - qg0;
        const float* kcur = sm + ((kt & 1) ? KS1_OFF : KS0_OFF);
        const float* vcur = sm + ((kt & 1) ? VS1_OFF : VS0_OFF);

        // ---- single wait + barrier per tile: buffers for THIS tile ready,
        //      all warps done reading the other buffers (safe to overwrite) ----
        CP_WAIT(0);
        __syncthreads();

        // ---- issue next tile's K/V cp.async into the other buffers ----
        if (kt < 15) {
            float* knxt = sm + (((kt + 1) & 1) ? KS1_OFF : KS0_OFF);
            float* vnxt = sm + (((kt + 1) & 1) ? VS1_OFF : VS0_OFF);
            #pragma unroll
            for (int l = 0; l < 8; l++) {
                int i = tid + l * NT, row = i >> 4, c4 = i & 15;
                cpa16((unsigned)__cvta_generic_to_shared(knxt + row * KS_STRIDE + c4 * 4),
                      kg + (kg0 + TK) * 16 + i);
                cpa16((unsigned)__cvta_generic_to_shared(vnxt + row * VS_STRIDE + c4 * 4),
                      vg + (kg0 + TK) * 16 + i);
            }
            CP_COMMIT();
        }

        // ---- mask LDGs for CURRENT tile (consumed after QK; latency hidden) ----
        int4 mm0[4], mm1[4];
        {
            const int4* p0 = (const int4*)(mrow0 + kg0) + 4 * u;
            const int4* p1 = (const int4*)(mrow1 + kg0) + 4 * u;
            #pragma unroll
            for (int l = 0; l < 4; l++) { mm0[l] = p0[l]; mm1[l] = p1[l]; }
        }

        // ---- QK^T from raw K buffer (tf32 cvt at fragment load) ----
        float c[8][4];
        #pragma unroll
        for (int j = 0; j < 8; j++) { c[j][0]=0.f; c[j][1]=0.f; c[j][2]=0.f; c[j][3]=0.f; }
        #pragma unroll
        for (int s = 0; s < 8; s++) {
            #pragma unroll
            for (int j = 0; j < 8; j++) {
                unsigned b0 = f2tf(kcur[(8*j + keysel) * KS_STRIDE + 8*s + u]);
                unsigned b1 = f2tf(kcur[(8*j + keysel) * KS_STRIDE + 8*s + u + 4]);
                mma_tf32(c[j], aq[s], b0, b1);
            }
        }

        // ---- assemble mask words via quad shuffles ----
        unsigned mw0a, mw0b, mw1a, mw1b;
        {
            unsigned b0 = pack16(mm0) << ((u & 1) * 16);
            unsigned b1 = pack16(mm1) << ((u & 1) * 16);
            b0 |= __shfl_xor_sync(0xffffffffu, b0, 1);
            b1 |= __shfl_xor_sync(0xffffffffu, b1, 1);
            unsigned o0 = __shfl_xor_sync(0xffffffffu, b0, 2);
            unsigned o1 = __shfl_xor_sync(0xffffffffu, b1, 2);
            mw0a = (u & 2) ? o0 : b0;  mw0b = (u & 2) ? b0 : o0;
            mw1a = (u & 2) ? o1 : b1;  mw1b = (u & 2) ? b1 : o1;
        }

        // ---- epilogue: p = exp(dot*0.125 + rp')   [rp' has -16 folded in] ----
        const bool nearT = (D >= -64) && (D <= 64);
        #pragma unroll
        for (int j = 0; j < 8; j++) {
            const int col0 = 8*j + u, col1 = col0 + 4;
            float rv00, rv01, rv10, rv11;
            if (nearT) {
                int i00 = min(max(D + col0 - r0, -64), 64) + 64;
                int i01 = min(max(D + col1 - r0, -64), 64) + 64;
                int i10 = min(max(D + col0 - r1, -64), 64) + 64;
                int i11 = min(max(D + col1 - r1, -64), 64) + 64;
                rv00 = rp[r0 * RP_STRIDE + i00]; rv01 = rp[r0 * RP_STRIDE + i01];
                rv10 = rp[r1 * RP_STRIDE + i10]; rv11 = rp[r1 * RP_STRIDE + i11];
            } else if (D > 0) {
                rv00 = rpp0; rv01 = rpp0; rv10 = rpp1; rv11 = rpp1;
            } else {
                rv00 = rpn0; rv01 = rpn0; rv10 = rpn1; rv11 = rpn1;
            }
            const unsigned w0 = (j < 4) ? mw0a : mw0b;
            const unsigned w1 = (j < 4) ? mw1a : mw1b;
            float p00 = ((w0 >> (col0 & 31)) & 1) ? 0.f : __expf(fmaf(c[j][0], 0.125f, rv00));
            float p01 = ((w0 >> (col1 & 31)) & 1) ? 0.f : __expf(fmaf(c[j][1], 0.125f, rv01));
            float p10 = ((w1 >> (col0 & 31)) & 1) ? 0.f : __expf(fmaf(c[j][2], 0.125f, rv10));
            float p11 = ((w1 >> (col1 & 31)) & 1) ? 0.f : __expf(fmaf(c[j][3], 0.125f, rv11));
            ps0 += p00 + p01;
            ps1 += p10 + p11;
            c[j][0] = p00; c[j][1] = p01; c[j][2] = p10; c[j][3] = p11;
        }

        // ---- PV: A frags renamed from P; V converted at fragment load ----
        #pragma unroll
        for (int s = 0; s < 8; s++) {
            unsigned a[4] = { f2tf(c[s][0]), f2tf(c[s][2]), f2tf(c[s][1]), f2tf(c[s][3]) };
            #pragma unroll
            for (int j = 0; j < 8; j++) {
                unsigned b0 = f2tf(vcur[(8*s + u)     * VS_STRIDE + 8*j + g]);
                unsigned b1 = f2tf(vcur[(8*s + u + 4) * VS_STRIDE + 8*j + g]);
                mma_tf32(co[j], a, b0, b1);
            }
        }
    }

    // ---- single softmax-denominator reduction (quad) ----
    ps0 += __shfl_xor_sync(0xffffffffu, ps0, 1);
    ps0 += __shfl_xor_sync(0xffffffffu, ps0, 2);
    ps1 += __shfl_xor_sync(0xffffffffu, ps1, 1);
    ps1 += __shfl_xor_sync(0xffffffffu, ps1, 2);

    // ---- finalize ----
    const float il0 = 1.0f / ps0, il1 = 1.0f / ps1;
    float* o0 = out + (size_t)(b * SS + qg0 + r0) * DD;
    float* o1 = out + (size_t)(b * SS + qg0 + r1) * DD;
    #pragma unroll
    for (int j = 0; j < 8; j++) {
        int col = 8*j + 2*u;
        float2 v0; v0.x = co[j][0] * il0; v0.y = co[j][1] * il0;
        float2 v1; v1.x = co[j][2] * il1; v1.y = co[j][3] * il1;
        *(float2*)(o0 + col) = v0;
        *(float2*)(o1 + col) = v1;
    }
}

extern "C" void kernel_launch(void* const* d_in, const int* in_sizes, int n_in,
                              void* d_out, int out_size) {
    const float* q    = (const float*)d_in[0];
    const float* k    = (const float*)d_in[1];
    const float* v    = (const float*)d_in[2];
    const int*   mask = (const int*)d_in[3];
    const float* pt   = (const float*)d_in[4];
    float*       out  = (float*)d_out;

    size_t smem = SMEM_FLOATS * sizeof(float);
    cudaFuncSetAttribute(attn_tc_kernel,
                         cudaFuncAttributeMaxDynamicSharedMemorySize, (int)smem);
    dim3 grid(SS / TQ, BB);
    attn_tc_kernel<<<grid, NT, smem>>>(q, k, v, mask, pt, out);
}

// round 14
// speedup vs baseline: 1.0048x; 1.0048x over previous
#include <cuda_runtime.h>
#include <cstdint>

#define BB 32
#define SS 1024
#define DD 64
#define TQ 64
#define TK 64
#define NT 128

#define KS_STRIDE 68
#define VS_STRIDE 72
#define RP_STRIDE 129
#define PT_STRIDE 136

// smem float offsets: K and V both double-buffered, pre-converted tf32 bits
#define KS0_OFF 0                             // 64 x 68
#define KS1_OFF (KS0_OFF + 64*KS_STRIDE)      // 4352
#define VS0_OFF (KS1_OFF + 64*KS_STRIDE)      // 8704, 64 x 72
#define VS1_OFF (VS0_OFF + 64*VS_STRIDE)      // 13312
#define RP_OFF  (VS1_OFF + 64*VS_STRIDE)      // 17920
#define SMEM_FLOATS (RP_OFF + 64*RP_STRIDE)   // 26176 floats = 104704 B -> 2 CTAs/SM
#define PT_OFF VS0_OFF                        // ptt aliases V buffers (8704 <= 9216)

#define TOTAL_ELEMS (BB * SS * DD)            // 2,097,152 floats = 8 MB per tensor

__device__ float g_ktf[TOTAL_ELEMS];          // K pre-converted to tf32 bit patterns
__device__ float g_vtf[TOTAL_ELEMS];          // V pre-converted to tf32 bit patterns

__device__ __forceinline__ unsigned f2tf(float f) {
    unsigned u; asm("cvt.rna.tf32.f32 %0, %1;" : "=r"(u) : "f"(f)); return u;
}

// ---- prepass: convert K and V to tf32 in gmem (one float4 of each per thread) ----
__global__ void cvt_kv_kernel(const float4* __restrict__ k, const float4* __restrict__ v) {
    int i = blockIdx.x * blockDim.x + threadIdx.x;   // float4 index
    float4 kv = k[i], vv = v[i];
    kv.x = __uint_as_float(f2tf(kv.x)); kv.y = __uint_as_float(f2tf(kv.y));
    kv.z = __uint_as_float(f2tf(kv.z)); kv.w = __uint_as_float(f2tf(kv.w));
    vv.x = __uint_as_float(f2tf(vv.x)); vv.y = __uint_as_float(f2tf(vv.y));
    vv.z = __uint_as_float(f2tf(vv.z)); vv.w = __uint_as_float(f2tf(vv.w));
    ((float4*)g_ktf)[i] = kv;
    ((float4*)g_vtf)[i] = vv;
}

__device__ __forceinline__ void mma_tf32(float c[4], const unsigned a[4],
                                         unsigned b0, unsigned b1) {
    asm volatile(
        "mma.sync.aligned.m16n8k8.row.col.f32.tf32.tf32.f32 "
        "{%0,%1,%2,%3}, {%4,%5,%6,%7}, {%8,%9}, {%0,%1,%2,%3};"
        : "+f"(c[0]), "+f"(c[1]), "+f"(c[2]), "+f"(c[3])
        : "r"(a[0]), "r"(a[1]), "r"(a[2]), "r"(a[3]), "r"(b0), "r"(b1));
}
__device__ __forceinline__ void cpa16(unsigned s, const void* g) {
    asm volatile("cp.async.cg.shared.global [%0], [%1], 16;" :: "r"(s), "l"(g));
}
#define CP_COMMIT() asm volatile("cp.async.commit_group;")
#define CP_WAIT(n)  asm volatile("cp.async.wait_group %0;" :: "n"(n))

// pack 16 ints (4 int4) into 16 mask bits
__device__ __forceinline__ unsigned pack16(const int4* m4) {
    unsigned bits = 0;
    #pragma unroll
    for (int l = 0; l < 4; l++) {
        int4 v = m4[l];
        unsigned nib = (unsigned)(v.x != 0) | ((unsigned)(v.y != 0) << 1)
                     | ((unsigned)(v.z != 0) << 2) | ((unsigned)(v.w != 0) << 3);
        bits |= nib << (4 * l);
    }
    return bits;
}

// rp-table GEMM chunk: stores PRE-SCALED values rp'[r][j] = (q[r,:].pt[j,:])*0.125 - 16
template<int NB0, int NBN>
__device__ __forceinline__ void rp_mma_chunk(const unsigned aq[8][4], const float* ptt,
                                             float* rp, int r0, int r1, int u, int g) {
    float c[NBN][4];
    #pragma unroll
    for (int n = 0; n < NBN; n++) { c[n][0]=0.f; c[n][1]=0.f; c[n][2]=0.f; c[n][3]=0.f; }
    #pragma unroll
    for (int s = 0; s < 8; s++) {
        #pragma unroll
        for (int n = 0; n < NBN; n++) {
            int jr = (NB0 + n) * 8 + g;
            unsigned b0 = __float_as_uint(ptt[(8*s + u)     * PT_STRIDE + jr]);
            unsigned b1 = __float_as_uint(ptt[(8*s + u + 4) * PT_STRIDE + jr]);
            mma_tf32(c[n], aq[s], b0, b1);
        }
    }
    #pragma unroll
    for (int n = 0; n < NBN; n++) {
        int col = (NB0 + n) * 8 + 2 * u;
        if (col <= 128) {
            rp[r0*RP_STRIDE + col] = fmaf(c[n][0], 0.125f, -16.f);
            rp[r1*RP_STRIDE + col] = fmaf(c[n][2], 0.125f, -16.f);
        }
        if (col + 1 <= 128) {
            rp[r0*RP_STRIDE + col + 1] = fmaf(c[n][1], 0.125f, -16.f);
            rp[r1*RP_STRIDE + col + 1] = fmaf(c[n][3], 0.125f, -16.f);
        }
    }
}

__global__ void __launch_bounds__(NT, 2)
attn_tc_kernel(const float* __restrict__ q,
               const int* __restrict__ mask,
               const float* __restrict__ pt,
               float* __restrict__ out) {
    extern __shared__ float sm[];
    float* rp  = sm + RP_OFF;
    float* ptt = sm + PT_OFF;

    const int tid  = threadIdx.x;
    const int lane = tid & 31;
    const int w    = tid >> 5;
    const int u    = lane & 3;
    const int g    = lane >> 2;
    const int qt   = blockIdx.x, b = blockIdx.y;
    const int qg0  = qt * TQ;
    const int r0   = 16 * w + g;
    const int r1   = r0 + 8;
    const int keysel = (g >> 1) + 4 * (g & 1);   // sigma(g)

    const float4* kg = (const float4*)(g_ktf + (size_t)b * SS * DD);
    const float4* vg = (const float4*)(g_vtf + (size_t)b * SS * DD);
    const int* mrow0 = mask + (size_t)(b * SS + qg0 + r0) * SS;
    const int* mrow1 = mask + (size_t)(b * SS + qg0 + r1) * SS;

    // ---- issue K0 cp.async FIRST (K region never aliased) -> overlaps rp phase ----
    {
        #pragma unroll
        for (int l = 0; l < 8; l++) {
            int i = tid + l * NT, row = i >> 4, c4 = i & 15;
            unsigned dst = (unsigned)__cvta_generic_to_shared(sm + KS0_OFF + row * KS_STRIDE + c4 * 4);
            cpa16(dst, kg + i);
        }
        CP_COMMIT();
    }

    // ---- phase 0: stage transposed tf32 pos_table (aliases V buffers) ----
    {
        const float4* ptg = (const float4*)pt;
        for (int i = tid; i < 129 * 16; i += NT) {
            int j = i >> 4, c0 = (i & 15) * 4;
            float4 p4 = ptg[i];
            ptt[(c0 + 0) * PT_STRIDE + j] = __uint_as_float(f2tf(p4.x));
            ptt[(c0 + 1) * PT_STRIDE + j] = __uint_as_float(f2tf(p4.y));
            ptt[(c0 + 2) * PT_STRIDE + j] = __uint_as_float(f2tf(p4.z));
            ptt[(c0 + 3) * PT_STRIDE + j] = __uint_as_float(f2tf(p4.w));
        }
        for (int i = tid; i < 64 * 7; i += NT)
            ptt[(i / 7) * PT_STRIDE + 129 + (i % 7)] = 0.f;
    }

    // ---- Q fragments straight from gmem ----
    unsigned aq[8][4];
    {
        const float* q0 = q + (size_t)(b * SS + qg0 + r0) * DD;
        const float* q1 = q + (size_t)(b * SS + qg0 + r1) * DD;
        #pragma unroll
        for (int s = 0; s < 8; s++) {
            aq[s][0] = f2tf(q0[8*s + u]);
            aq[s][1] = f2tf(q1[8*s + u]);
            aq[s][2] = f2tf(q0[8*s + u + 4]);
            aq[s][3] = f2tf(q1[8*s + u + 4]);
        }
    }
    __syncthreads();

    // ---- phase 1: rp table via MMA (pre-scaled: *0.125 - 16) ----
    rp_mma_chunk<0, 9>(aq, ptt, rp, r0, r1, u, g);
    rp_mma_chunk<9, 8>(aq, ptt, rp, r0, r1, u, g);
    __syncthreads();   // ptt (V-buffer alias) dead after this point

    const float rpn0 = rp[r0 * RP_STRIDE + 0],   rpn1 = rp[r1 * RP_STRIDE + 0];
    const float rpp0 = rp[r0 * RP_STRIDE + 128], rpp1 = rp[r1 * RP_STRIDE + 128];

    // ---- issue V0 cp.async (V region now free) ----
    {
        #pragma unroll
        for (int l = 0; l < 8; l++) {
            int i = tid + l * NT, row = i >> 4, c4 = i & 15;
            unsigned dst = (unsigned)__cvta_generic_to_shared(sm + VS0_OFF + row * VS_STRIDE + c4 * 4);
            cpa16(dst, vg + i);
        }
        CP_COMMIT();
    }

    float ps0 = 0.f, ps1 = 0.f;    // per-thread softmax denominators
    float co[8][4];
    #pragma unroll
    for (int j = 0; j < 8; j++) { co[j][0]=0.f; co[j][1]=0.f; co[j][2]=0.f; co[j][3]=0.f; }

    for (int kt = 0; kt < SS / TK; kt++) {
        const int kg0 = kt * TK;
        const int D   = kg0 - qg0;
        const float* kcur = sm + ((kt & 1) ? KS1_OFF : KS0_OFF);
        const float* vcur = sm + ((kt & 1) ? VS1_OFF : VS0_OFF);

        // ---- single wait + barrier per tile ----
        CP_WAIT(0);
        __syncthreads();

        // ---- issue next tile's K/V cp.async into the other buffers ----
        if (kt < 15) {
            float* knxt = sm + (((kt + 1) & 1) ? KS1_OFF : KS0_OFF);
            float* vnxt = sm + (((kt + 1) & 1) ? VS1_OFF : VS0_OFF);
            #pragma unroll
            for (int l = 0; l < 8; l++) {
                int i = tid + l * NT, row = i >> 4, c4 = i & 15;
                cpa16((unsigned)__cvta_generic_to_shared(knxt + row * KS_STRIDE + c4 * 4),
                      kg + (kg0 + TK) * 16 + i);
                cpa16((unsigned)__cvta_generic_to_shared(vnxt + row * VS_STRIDE + c4 * 4),
                      vg + (kg0 + TK) * 16 + i);
            }
            CP_COMMIT();
        }

        // ---- mask LDGs for CURRENT tile (consumed after QK; latency hidden) ----
        int4 mm0[4], mm1[4];
        {
            const int4* p0 = (const int4*)(mrow0 + kg0) + 4 * u;
            const int4* p1 = (const int4*)(mrow1 + kg0) + 4 * u;
            #pragma unroll
            for (int l = 0; l < 4; l++) { mm0[l] = p0[l]; mm1[l] = p1[l]; }
        }

        // ---- QK^T: K fragments are pre-converted tf32 bits (no cvt) ----
        float c[8][4];
        #pragma unroll
        for (int j = 0; j < 8; j++) { c[j][0]=0.f; c[j][1]=0.f; c[j][2]=0.f; c[j][3]=0.f; }
        #pragma unroll
        for (int s = 0; s < 8; s++) {
            #pragma unroll
            for (int j = 0; j < 8; j++) {
                unsigned b0 = __float_as_uint(kcur[(8*j + keysel) * KS_STRIDE + 8*s + u]);
                unsigned b1 = __float_as_uint(kcur[(8*j + keysel) * KS_STRIDE + 8*s + u + 4]);
                mma_tf32(c[j], aq[s], b0, b1);
            }
        }

        // ---- assemble mask words via quad shuffles ----
        unsigned mw0a, mw0b, mw1a, mw1b;
        {
            unsigned b0 = pack16(mm0) << ((u & 1) * 16);
            unsigned b1 = pack16(mm1) << ((u & 1) * 16);
            b0 |= __shfl_xor_sync(0xffffffffu, b0, 1);
            b1 |= __shfl_xor_sync(0xffffffffu, b1, 1);
            unsigned o0 = __shfl_xor_sync(0xffffffffu, b0, 2);
            unsigned o1 = __shfl_xor_sync(0xffffffffu, b1, 2);
            mw0a = (u & 2) ? o0 : b0;  mw0b = (u & 2) ? b0 : o0;
            mw1a = (u & 2) ? o1 : b1;  mw1b = (u & 2) ? b1 : o1;
        }

        // ---- epilogue: p = exp(dot*0.125 + rp')   [rp' has -16 folded in] ----
        const bool nearT = (D >= -64) && (D <= 64);
        #pragma unroll
        for (int j = 0; j < 8; j++) {
            const int col0 = 8*j + u, col1 = col0 + 4;
            float rv00, rv01, rv10, rv11;
            if (nearT) {
                int i00 = min(max(D + col0 - r0, -64), 64) + 64;
                int i01 = min(max(D + col1 - r0, -64), 64) + 64;
                int i10 = min(max(D + col0 - r1, -64), 64) + 64;
                int i11 = min(max(D + col1 - r1, -64), 64) + 64;
                rv00 = rp[r0 * RP_STRIDE + i00]; rv01 = rp[r0 * RP_STRIDE + i01];
                rv10 = rp[r1 * RP_STRIDE + i10]; rv11 = rp[r1 * RP_STRIDE + i11];
            } else if (D > 0) {
                rv00 = rpp0; rv01 = rpp0; rv10 = rpp1; rv11 = rpp1;
            } else {
                rv00 = rpn0; rv01 = rpn0; rv10 = rpn1; rv11 = rpn1;
            }
            const unsigned w0 = (j < 4) ? mw0a : mw0b;
            const unsigned w1 = (j < 4) ? mw1a : mw1b;
            float p00 = ((w0 >> (col0 & 31)) & 1) ? 0.f : __expf(fmaf(c[j][0], 0.125f, rv00));
            float p01 = ((w0 >> (col1 & 31)) & 1) ? 0.f : __expf(fmaf(c[j][1], 0.125f, rv01));
            float p10 = ((w1 >> (col0 & 31)) & 1) ? 0.f : __expf(fmaf(c[j][2], 0.125f, rv10));
            float p11 = ((w1 >> (col1 & 31)) & 1) ? 0.f : __expf(fmaf(c[j][3], 0.125f, rv11));
            ps0 += p00 + p01;
            ps1 += p10 + p11;
            c[j][0] = p00; c[j][1] = p01; c[j][2] = p10; c[j][3] = p11;
        }

        // ---- PV: A frags = cvt of P (only remaining cvts); V pre-converted ----
        #pragma unroll
        for (int s = 0; s < 8; s++) {
            unsigned a[4] = { f2tf(c[s][0]), f2tf(c[s][2]), f2tf(c[s][1]), f2tf(c[s][3]) };
            #pragma unroll
            for (int j = 0; j < 8; j++) {
                unsigned b0 = __float_as_uint(vcur[(8*s + u)     * VS_STRIDE + 8*j + g]);
                unsigned b1 = __float_as_uint(vcur[(8*s + u + 4) * VS_STRIDE + 8*j + g]);
                mma_tf32(co[j], a, b0, b1);
            }
        }
    }

    // ---- single softmax-denominator reduction (quad) ----
    ps0 += __shfl_xor_sync(0xffffffffu, ps0, 1);
    ps0 += __shfl_xor_sync(0xffffffffu, ps0, 2);
    ps1 += __shfl_xor_sync(0xffffffffu, ps1, 1);
    ps1 += __shfl_xor_sync(0xffffffffu, ps1, 2);

    // ---- finalize ----
    const float il0 = 1.0f / ps0, il1 = 1.0f / ps1;
    float* o0 = out + (size_t)(b * SS + qg0 + r0) * DD;
    float* o1 = out + (size_t)(b * SS + qg0 + r1) * DD;
    #pragma unroll
    for (int j = 0; j < 8; j++) {
        int col = 8*j + 2*u;
        float2 v0; v0.x = co[j][0] * il0; v0.y = co[j][1] * il0;
        float2 v1; v1.x = co[j][2] * il1; v1.y = co[j][3] * il1;
        *(float2*)(o0 + col) = v0;
        *(float2*)(o1 + col) = v1;
    }
}

extern "C" void kernel_launch(void* const* d_in, const int* in_sizes, int n_in,
                              void* d_out, int out_size) {
    const float* q    = (const float*)d_in[0];
    const float* k    = (const float*)d_in[1];
    const float* v    = (const float*)d_in[2];
    const int*   mask = (const int*)d_in[3];
    const float* pt   = (const float*)d_in[4];
    float*       out  = (float*)d_out;

    // prepass: K,V -> tf32 scratch (524288 float4 pairs)
    cvt_kv_kernel<<<(TOTAL_ELEMS / 4) / 256, 256>>>((const float4*)k, (const float4*)v);

    size_t smem = SMEM_FLOATS * sizeof(float);
    cudaFuncSetAttribute(attn_tc_kernel,
                         cudaFuncAttributeMaxDynamicSharedMemorySize, (int)smem);
    dim3 grid(SS / TQ, BB);
    attn_tc_kernel<<<grid, NT, smem>>>(q, mask, pt, out);
}

// round 15
// speedup vs baseline: 1.0478x; 1.0428x over previous
#include <cuda_runtime.h>
#include <cstdint>

#define BB 32
#define SS 1024
#define DD 64
#define TQ 64
#define TK 64
#define NT 256

#define KS_STRIDE 68
#define VS_STRIDE 72
#define RP_STRIDE 129
#define PT_STRIDE 136
#define RED_STRIDE 66

// smem float offsets: K and V double-buffered, pre-converted tf32 bits
#define KS0_OFF 0                             // 64 x 68
#define KS1_OFF (KS0_OFF + 64*KS_STRIDE)      // 4352
#define VS0_OFF (KS1_OFF + 64*KS_STRIDE)      // 8704, 64 x 72
#define VS1_OFF (VS0_OFF + 64*VS_STRIDE)      // 13312
#define RP_OFF  (VS1_OFF + 64*VS_STRIDE)      // 17920
#define SMEM_FLOATS (RP_OFF + 64*RP_STRIDE)   // 26176 floats = 104704 B -> 2 CTAs/SM
#define PT_OFF VS0_OFF                        // ptt aliases V buffers (8704 <= 9216)

#define TOTAL_ELEMS (BB * SS * DD)            // 8 MB per tensor

__device__ float g_ktf[TOTAL_ELEMS];          // K pre-converted to tf32 bit patterns
__device__ float g_vtf[TOTAL_ELEMS];          // V pre-converted to tf32 bit patterns

__device__ __forceinline__ unsigned f2tf(float f) {
    unsigned u; asm("cvt.rna.tf32.f32 %0, %1;" : "=r"(u) : "f"(f)); return u;
}

// ---- prepass: convert K and V to tf32 in gmem ----
__global__ void cvt_kv_kernel(const float4* __restrict__ k, const float4* __restrict__ v) {
    int i = blockIdx.x * blockDim.x + threadIdx.x;
    float4 kv = k[i], vv = v[i];
    kv.x = __uint_as_float(f2tf(kv.x)); kv.y = __uint_as_float(f2tf(kv.y));
    kv.z = __uint_as_float(f2tf(kv.z)); kv.w = __uint_as_float(f2tf(kv.w));
    vv.x = __uint_as_float(f2tf(vv.x)); vv.y = __uint_as_float(f2tf(vv.y));
    vv.z = __uint_as_float(f2tf(vv.z)); vv.w = __uint_as_float(f2tf(vv.w));
    ((float4*)g_ktf)[i] = kv;
    ((float4*)g_vtf)[i] = vv;
}

__device__ __forceinline__ void mma_tf32(float c[4], const unsigned a[4],
                                         unsigned b0, unsigned b1) {
    asm volatile(
        "mma.sync.aligned.m16n8k8.row.col.f32.tf32.tf32.f32 "
        "{%0,%1,%2,%3}, {%4,%5,%6,%7}, {%8,%9}, {%0,%1,%2,%3};"
        : "+f"(c[0]), "+f"(c[1]), "+f"(c[2]), "+f"(c[3])
        : "r"(a[0]), "r"(a[1]), "r"(a[2]), "r"(a[3]), "r"(b0), "r"(b1));
}
__device__ __forceinline__ void cpa16(unsigned s, const void* g) {
    asm volatile("cp.async.cg.shared.global [%0], [%1], 16;" :: "r"(s), "l"(g));
}
#define CP_COMMIT() asm volatile("cp.async.commit_group;")
#define CP_WAIT(n)  asm volatile("cp.async.wait_group %0;" :: "n"(n))

// pack 8 ints (2 int4) into 8 mask bits
__device__ __forceinline__ unsigned pack8(int4 a, int4 b) {
    return (unsigned)(a.x != 0)        | ((unsigned)(a.y != 0) << 1)
         | ((unsigned)(a.z != 0) << 2) | ((unsigned)(a.w != 0) << 3)
         | ((unsigned)(b.x != 0) << 4) | ((unsigned)(b.y != 0) << 5)
         | ((unsigned)(b.z != 0) << 6) | ((unsigned)(b.w != 0) << 7);
}

// rp-table GEMM chunk: stores PRE-SCALED values rp'[r][j] = (q[r,:].pt[j,:])*0.125 - 16
template<int NB0, int NBN>
__device__ __forceinline__ void rp_mma_chunk(const unsigned aq[8][4], const float* ptt,
                                             float* rp, int r0, int r1, int u, int g) {
    float c[NBN][4];
    #pragma unroll
    for (int n = 0; n < NBN; n++) { c[n][0]=0.f; c[n][1]=0.f; c[n][2]=0.f; c[n][3]=0.f; }
    #pragma unroll
    for (int s = 0; s < 8; s++) {
        #pragma unroll
        for (int n = 0; n < NBN; n++) {
            int jr = (NB0 + n) * 8 + g;
            unsigned b0 = __float_as_uint(ptt[(8*s + u)     * PT_STRIDE + jr]);
            unsigned b1 = __float_as_uint(ptt[(8*s + u + 4) * PT_STRIDE + jr]);
            mma_tf32(c[n], aq[s], b0, b1);
        }
    }
    #pragma unroll
    for (int n = 0; n < NBN; n++) {
        int col = (NB0 + n) * 8 + 2 * u;
        if (col <= 128) {
            rp[r0*RP_STRIDE + col] = fmaf(c[n][0], 0.125f, -16.f);
            rp[r1*RP_STRIDE + col] = fmaf(c[n][2], 0.125f, -16.f);
        }
        if (col + 1 <= 128) {
            rp[r0*RP_STRIDE + col + 1] = fmaf(c[n][1], 0.125f, -16.f);
            rp[r1*RP_STRIDE + col + 1] = fmaf(c[n][3], 0.125f, -16.f);
        }
    }
}

__global__ void __launch_bounds__(NT, 2)
attn_tc_kernel(const float* __restrict__ q,
               const int* __restrict__ mask,
               const float* __restrict__ pt,
               float* __restrict__ out) {
    extern __shared__ float sm[];
    float* rp  = sm + RP_OFF;
    float* ptt = sm + PT_OFF;

    const int tid  = threadIdx.x;
    const int lane = tid & 31;
    const int w    = tid >> 5;       // warp 0..7
    const int wq   = w & 3;          // row group
    const int h    = w >> 2;         // key half (0: keys 0-31, 1: keys 32-63)
    const int u    = lane & 3;
    const int g    = lane >> 2;
    const int qt   = blockIdx.x, b = blockIdx.y;
    const int qg0  = qt * TQ;
    const int r0   = 16 * wq + g;
    const int r1   = r0 + 8;
    const int keysel = (g >> 1) + 4 * (g & 1);   // sigma(g)

    const float4* kg = (const float4*)(g_ktf + (size_t)b * SS * DD);
    const float4* vg = (const float4*)(g_vtf + (size_t)b * SS * DD);
    const int* mrow0 = mask + (size_t)(b * SS + qg0 + r0) * SS;
    const int* mrow1 = mask + (size_t)(b * SS + qg0 + r1) * SS;

    // ---- issue K0 cp.async FIRST (K region never aliased) ----
    {
        #pragma unroll
        for (int l = 0; l < 4; l++) {
            int i = tid + l * NT, row = i >> 4, c4 = i & 15;
            cpa16((unsigned)__cvta_generic_to_shared(sm + KS0_OFF + row * KS_STRIDE + c4 * 4),
                  kg + i);
        }
        CP_COMMIT();
    }

    // ---- phase 0: stage transposed tf32 pos_table (aliases V buffers) ----
    {
        const float4* ptg = (const float4*)pt;
        for (int i = tid; i < 129 * 16; i += NT) {
            int j = i >> 4, c0 = (i & 15) * 4;
            float4 p4 = ptg[i];
            ptt[(c0 + 0) * PT_STRIDE + j] = __uint_as_float(f2tf(p4.x));
            ptt[(c0 + 1) * PT_STRIDE + j] = __uint_as_float(f2tf(p4.y));
            ptt[(c0 + 2) * PT_STRIDE + j] = __uint_as_float(f2tf(p4.z));
            ptt[(c0 + 3) * PT_STRIDE + j] = __uint_as_float(f2tf(p4.w));
        }
        for (int i = tid; i < 64 * 7; i += NT)
            ptt[(i / 7) * PT_STRIDE + 129 + (i % 7)] = 0.f;
    }

    // ---- Q fragments straight from gmem (both key-half warp groups hold same rows) ----
    unsigned aq[8][4];
    {
        const float* q0 = q + (size_t)(b * SS + qg0 + r0) * DD;
        const float* q1 = q + (size_t)(b * SS + qg0 + r1) * DD;
        #pragma unroll
        for (int s = 0; s < 8; s++) {
            aq[s][0] = f2tf(q0[8*s + u]);
            aq[s][1] = f2tf(q1[8*s + u]);
            aq[s][2] = f2tf(q0[8*s + u + 4]);
            aq[s][3] = f2tf(q1[8*s + u + 4]);
        }
    }
    __syncthreads();

    // ---- phase 1: rp table via MMA, split across key-half warp groups ----
    if (h == 0) rp_mma_chunk<0, 9>(aq, ptt, rp, r0, r1, u, g);
    else        rp_mma_chunk<9, 8>(aq, ptt, rp, r0, r1, u, g);
    __syncthreads();   // ptt (V-buffer alias) dead after this point

    const float rpn0 = rp[r0 * RP_STRIDE + 0],   rpn1 = rp[r1 * RP_STRIDE + 0];
    const float rpp0 = rp[r0 * RP_STRIDE + 128], rpp1 = rp[r1 * RP_STRIDE + 128];

    // ---- issue V0 cp.async (V region now free) ----
    {
        #pragma unroll
        for (int l = 0; l < 4; l++) {
            int i = tid + l * NT, row = i >> 4, c4 = i & 15;
            cpa16((unsigned)__cvta_generic_to_shared(sm + VS0_OFF + row * VS_STRIDE + c4 * 4),
                  vg + i);
        }
        CP_COMMIT();
    }

    float ps0 = 0.f, ps1 = 0.f;    // per-thread partial denominators (key half)
    float co[8][4];                // partial output accumulators (key half)
    #pragma unroll
    for (int j = 0; j < 8; j++) { co[j][0]=0.f; co[j][1]=0.f; co[j][2]=0.f; co[j][3]=0.f; }

    for (int kt = 0; kt < SS / TK; kt++) {
        const int kg0 = kt * TK;
        const int D   = kg0 - qg0;
        const float* kcur = sm + ((kt & 1) ? KS1_OFF : KS0_OFF);
        const float* vcur = sm + ((kt & 1) ? VS1_OFF : VS0_OFF);

        // ---- single wait + barrier per tile ----
        CP_WAIT(0);
        __syncthreads();

        // ---- issue next tile's K/V cp.async into the other buffers ----
        if (kt < 15) {
            float* knxt = sm + (((kt + 1) & 1) ? KS1_OFF : KS0_OFF);
            float* vnxt = sm + (((kt + 1) & 1) ? VS1_OFF : VS0_OFF);
            #pragma unroll
            for (int l = 0; l < 4; l++) {
                int i = tid + l * NT, row = i >> 4, c4 = i & 15;
                cpa16((unsigned)__cvta_generic_to_shared(knxt + row * KS_STRIDE + c4 * 4),
                      kg + (kg0 + TK) * 16 + i);
                cpa16((unsigned)__cvta_generic_to_shared(vnxt + row * VS_STRIDE + c4 * 4),
                      vg + (kg0 + TK) * 16 + i);
            }
            CP_COMMIT();
        }

        // ---- mask LDGs for this warp's key half (keys 32h..32h+31) ----
        int4 ma0, ma1, mb0, mb1;
        {
            const int4* p0 = (const int4*)(mrow0 + kg0 + 32 * h) + 2 * u;
            const int4* p1 = (const int4*)(mrow1 + kg0 + 32 * h) + 2 * u;
            ma0 = p0[0]; ma1 = p0[1];
            mb0 = p1[0]; mb1 = p1[1];
        }

        // ---- QK^T: this warp's 4 key blocks jj = 4h + jl ----
        float c[4][4];
        #pragma unroll
        for (int jl = 0; jl < 4; jl++) { c[jl][0]=0.f; c[jl][1]=0.f; c[jl][2]=0.f; c[jl][3]=0.f; }
        #pragma unroll
        for (int s = 0; s < 8; s++) {
            #pragma unroll
            for (int jl = 0; jl < 4; jl++) {
                int jj = 4 * h + jl;
                unsigned b0 = __float_as_uint(kcur[(8*jj + keysel) * KS_STRIDE + 8*s + u]);
                unsigned b1 = __float_as_uint(kcur[(8*jj + keysel) * KS_STRIDE + 8*s + u + 4]);
                mma_tf32(c[jl], aq[s], b0, b1);
            }
        }

        // ---- assemble 32-bit mask words for the key half (quad OR-reduce) ----
        unsigned mw0, mw1;
        {
            unsigned b0 = pack8(ma0, ma1) << (8 * u);
            unsigned b1 = pack8(mb0, mb1) << (8 * u);
            b0 |= __shfl_xor_sync(0xffffffffu, b0, 1);
            b1 |= __shfl_xor_sync(0xffffffffu, b1, 1);
            b0 |= __shfl_xor_sync(0xffffffffu, b0, 2);
            b1 |= __shfl_xor_sync(0xffffffffu, b1, 2);
            mw0 = b0; mw1 = b1;
        }

        // ---- epilogue: p = exp(dot*0.125 + rp')   [rp' has -16 folded in] ----
        const bool nearT = (D >= -64) && (D <= 64);
        #pragma unroll
        for (int jl = 0; jl < 4; jl++) {
            const int lc0 = 8*jl + u, lc1 = lc0 + 4;        // local bit index
            const int col0 = 32*h + lc0, col1 = 32*h + lc1; // global key in tile
            float rv00, rv01, rv10, rv11;
            if (nearT) {
                int i00 = min(max(D + col0 - r0, -64), 64) + 64;
                int i01 = min(max(D + col1 - r0, -64), 64) + 64;
                int i10 = min(max(D + col0 - r1, -64), 64) + 64;
                int i11 = min(max(D + col1 - r1, -64), 64) + 64;
                rv00 = rp[r0 * RP_STRIDE + i00]; rv01 = rp[r0 * RP_STRIDE + i01];
                rv10 = rp[r1 * RP_STRIDE + i10]; rv11 = rp[r1 * RP_STRIDE + i11];
            } else if (D > 0) {
                rv00 = rpp0; rv01 = rpp0; rv10 = rpp1; rv11 = rpp1;
            } else {
                rv00 = rpn0; rv01 = rpn0; rv10 = rpn1; rv11 = rpn1;
            }
            float p00 = ((mw0 >> lc0) & 1) ? 0.f : __expf(fmaf(c[jl][0], 0.125f, rv00));
            float p01 = ((mw0 >> lc1) & 1) ? 0.f : __expf(fmaf(c[jl][1], 0.125f, rv01));
            float p10 = ((mw1 >> lc0) & 1) ? 0.f : __expf(fmaf(c[jl][2], 0.125f, rv10));
            float p11 = ((mw1 >> lc1) & 1) ? 0.f : __expf(fmaf(c[jl][3], 0.125f, rv11));
            ps0 += p00 + p01;
            ps1 += p10 + p11;
            c[jl][0] = p00; c[jl][1] = p01; c[jl][2] = p10; c[jl][3] = p11;
        }

        // ---- PV over this warp's key half: s blocks ss = 4h + sl ----
        #pragma unroll
        for (int sl = 0; sl < 4; sl++) {
            int ss = 4 * h + sl;
            unsigned a[4] = { f2tf(c[sl][0]), f2tf(c[sl][2]), f2tf(c[sl][1]), f2tf(c[sl][3]) };
            #pragma unroll
            for (int j = 0; j < 8; j++) {
                unsigned b0 = __float_as_uint(vcur[(8*ss + u)     * VS_STRIDE + 8*j + g]);
                unsigned b1 = __float_as_uint(vcur[(8*ss + u + 4) * VS_STRIDE + 8*j + g]);
                mma_tf32(co[j], a, b0, b1);
            }
        }
    }

    // ---- quad reduction of partial denominators (within key half) ----
    ps0 += __shfl_xor_sync(0xffffffffu, ps0, 1);
    ps0 += __shfl_xor_sync(0xffffffffu, ps0, 2);
    ps1 += __shfl_xor_sync(0xffffffffu, ps1, 1);
    ps1 += __shfl_xor_sync(0xffffffffu, ps1, 2);

    // ---- cross-half reduction via smem (reuses dead rp region) ----
    float* red   = sm + RP_OFF;            // 64 x 66
    float* psred = red + 64 * RED_STRIDE;  // 64
    __syncthreads();   // everyone done with rp / buffers
    if (h == 1) {
        #pragma unroll
        for (int j = 0; j < 8; j++) {
            int col = 8*j + 2*u;
            red[r0 * RED_STRIDE + col]     = co[j][0];
            red[r0 * RED_STRIDE + col + 1] = co[j][1];
            red[r1 * RED_STRIDE + col]     = co[j][2];
            red[r1 * RED_STRIDE + col + 1] = co[j][3];
        }
        if (u == 0) { psred[r0] = ps0; psred[r1] = ps1; }
    }
    __syncthreads();
    if (h == 0) {
        const float il0 = 1.0f / (ps0 + psred[r0]);
        const float il1 = 1.0f / (ps1 + psred[r1]);
        float* o0 = out + (size_t)(b * SS + qg0 + r0) * DD;
        float* o1 = out + (size_t)(b * SS + qg0 + r1) * DD;
        #pragma unroll
        for (int j = 0; j < 8; j++) {
            int col = 8*j + 2*u;
            float2 v0, v1;
            v0.x = (co[j][0] + red[r0 * RED_STRIDE + col])     * il0;
            v0.y = (co[j][1] + red[r0 * RED_STRIDE + col + 1]) * il0;
            v1.x = (co[j][2] + red[r1 * RED_STRIDE + col])     * il1;
            v1.y = (co[j][3] + red[r1 * RED_STRIDE + col + 1]) * il1;
            *(float2*)(o0 + col) = v0;
            *(float2*)(o1 + col) = v1;
        }
    }
}

extern "C" void kernel_launch(void* const* d_in, const int* in_sizes, int n_in,
                              void* d_out, int out_size) {
    const float* q    = (const float*)d_in[0];
    const float* k    = (const float*)d_in[1];
    const float* v    = (const float*)d_in[2];
    const int*   mask = (const int*)d_in[3];
    const float* pt   = (const float*)d_in[4];
    float*       out  = (float*)d_out;

    cvt_kv_kernel<<<(TOTAL_ELEMS / 4) / 256, 256>>>((const float4*)k, (const float4*)v);

    size_t smem = SMEM_FLOATS * sizeof(float);
    cudaFuncSetAttribute(attn_tc_kernel,
                         cudaFuncAttributeMaxDynamicSharedMemorySize, (int)smem);
    dim3 grid(SS / TQ, BB);
    attn_tc_kernel<<<grid, NT, smem>>>(q, mask, pt, out);
}

// round 17
// speedup vs baseline: 1.5074x; 1.4386x over previous
#include <cuda_runtime.h>
#include <cuda_fp16.h>
#include <cstdint>

#define BB 32
#define SS 1024
#define DD 64
#define TQ 64
#define TK 64
#define NT 256

#define KH_STRIDE 72    // halves per K smem row
#define VT_STRIDE 72    // halves per V^T smem row
#define PT_STRIDE 68    // halves per pt smem row
#define RP_STRIDE 129
#define RED_STRIDE 66

// smem float offsets — each K/V tile is 64 x 72 halves = 4608 halves = 2304 FLOATS
#define KS0_OFF 0
#define KS1_OFF (KS0_OFF + 2304)
#define VT0_OFF (KS1_OFF + 2304)               // V^T tile [dim][key]
#define VT1_OFF (VT0_OFF + 2304)
#define PTT_OFF (VT1_OFF + 2304)               // 129 x 68 halves = 4386 floats
#define RP_OFF  (PTT_OFF + 4386)
#define SMEM_FLOATS (RP_OFF + 64*RP_STRIDE)    // 21858 floats = 87432 B -> 2 CTAs/SM

#define TOTAL_ELEMS (BB * SS * DD)

__device__ __half g_kh[TOTAL_ELEMS];           // K fp16, [b][key][dim]
__device__ __half g_vth[TOTAL_ELEMS];          // V fp16 transposed, [b][dim][key]

// ---- prepass 1: K -> fp16 (elementwise, coalesced) ----
__global__ void cvt_k_kernel(const float4* __restrict__ k) {
    int i = blockIdx.x * blockDim.x + threadIdx.x;
    float4 kv = k[i];
    __half2* dst = (__half2*)g_kh;
    dst[2*i]   = __floats2half2_rn(kv.x, kv.y);
    dst[2*i+1] = __floats2half2_rn(kv.z, kv.w);
}

// ---- prepass 2: V -> fp16 transposed via smem tile (coalesced both sides) ----
__global__ void cvt_vt_kernel(const float4* __restrict__ v) {
    __shared__ __half tile[64][68];   // [dim][key]
    int b = blockIdx.x >> 4, t = blockIdx.x & 15;
    int tid = threadIdx.x;
    const float4* src = v + ((size_t)(b * SS + t * 64) * DD) / 4;
    #pragma unroll
    for (int l = 0; l < 4; l++) {
        int i = tid + l * 256;         // float4 index, 0..1023
        int key = i >> 4, c4 = i & 15;
        float4 val = src[i];
        tile[4*c4+0][key] = __float2half_rn(val.x);
        tile[4*c4+1][key] = __float2half_rn(val.y);
        tile[4*c4+2][key] = __float2half_rn(val.z);
        tile[4*c4+3][key] = __float2half_rn(val.w);
    }
    __syncthreads();
    __half2* dst = (__half2*)(g_vth + (size_t)b * DD * SS);
    #pragma unroll
    for (int l = 0; l < 8; l++) {
        int idx = tid + l * 256;       // half2 index, 0..2047
        int dim = idx >> 5, p = idx & 31;
        dst[(size_t)dim * (SS/2) + t * 32 + p] =
            __halves2half2(tile[dim][2*p], tile[dim][2*p+1]);
    }
}

__device__ __forceinline__ unsigned packh2(float lo, float hi) {
    __half2 h = __floats2half2_rn(lo, hi);
    return *(unsigned*)&h;
}
__device__ __forceinline__ void mma_f16(float c[4], const unsigned a[4],
                                        unsigned b0, unsigned b1) {
    asm volatile(
        "mma.sync.aligned.m16n8k16.row.col.f32.f16.f16.f32 "
        "{%0,%1,%2,%3}, {%4,%5,%6,%7}, {%8,%9}, {%0,%1,%2,%3};"
        : "+f"(c[0]), "+f"(c[1]), "+f"(c[2]), "+f"(c[3])
        : "r"(a[0]), "r"(a[1]), "r"(a[2]), "r"(a[3]), "r"(b0), "r"(b1));
}
__device__ __forceinline__ void cpa16(unsigned s, const void* g) {
    asm volatile("cp.async.cg.shared.global [%0], [%1], 16;" :: "r"(s), "l"(g));
}
#define CP_COMMIT() asm volatile("cp.async.commit_group;")
#define CP_WAIT(n)  asm volatile("cp.async.wait_group %0;" :: "n"(n))

__device__ __forceinline__ unsigned pack8(int4 a, int4 b) {
    return (unsigned)(a.x != 0)        | ((unsigned)(a.y != 0) << 1)
         | ((unsigned)(a.z != 0) << 2) | ((unsigned)(a.w != 0) << 3)
         | ((unsigned)(b.x != 0) << 4) | ((unsigned)(b.y != 0) << 5)
         | ((unsigned)(b.z != 0) << 6) | ((unsigned)(b.w != 0) << 7);
}

// rp-table GEMM chunk (fp16): stores rp'[r][j] = (q[r,:].pt[j,:])*0.125 - 4
template<int NB0, int NBN>
__device__ __forceinline__ void rp_mma_chunk(const unsigned aq[4][4], const __half* hpt,
                                             float* rp, int r0, int r1, int u, int g) {
    float c[NBN][4];
    #pragma unroll
    for (int n = 0; n < NBN; n++) { c[n][0]=0.f; c[n][1]=0.f; c[n][2]=0.f; c[n][3]=0.f; }
    #pragma unroll
    for (int s = 0; s < 4; s++) {
        #pragma unroll
        for (int n = 0; n < NBN; n++) {
            int jr = (NB0 + n) * 8 + g;
            unsigned b0 = *(const unsigned*)(hpt + jr * PT_STRIDE + 16*s + 2*u);
            unsigned b1 = *(const unsigned*)(hpt + jr * PT_STRIDE + 16*s + 2*u + 8);
            mma_f16(c[n], aq[s], b0, b1);
        }
    }
    #pragma unroll
    for (int n = 0; n < NBN; n++) {
        int col = (NB0 + n) * 8 + 2 * u;
        if (col <= 128) {
            rp[r0*RP_STRIDE + col] = fmaf(c[n][0], 0.125f, -4.f);
            rp[r1*RP_STRIDE + col] = fmaf(c[n][2], 0.125f, -4.f);
        }
        if (col + 1 <= 128) {
            rp[r0*RP_STRIDE + col + 1] = fmaf(c[n][1], 0.125f, -4.f);
            rp[r1*RP_STRIDE + col + 1] = fmaf(c[n][3], 0.125f, -4.f);
        }
    }
}

__global__ void __launch_bounds__(NT, 2)
attn_tc_kernel(const float* __restrict__ q,
               const int* __restrict__ mask,
               const float* __restrict__ pt,
               float* __restrict__ out) {
    extern __shared__ float sm[];
    float* rp = sm + RP_OFF;
    __half* hpt = (__half*)(sm + PTT_OFF);

    const int tid  = threadIdx.x;
    const int lane = tid & 31;
    const int w    = tid >> 5;       // warp 0..7
    const int wq   = w & 3;          // row group
    const int h    = w >> 2;         // key half
    const int u    = lane & 3;
    const int g    = lane >> 2;
    const int qt   = blockIdx.x, b = blockIdx.y;
    const int qg0  = qt * TQ;
    const int r0   = 16 * wq + g;
    const int r1   = r0 + 8;

    const __half* kgh = g_kh  + (size_t)b * SS * DD;   // [key][dim]
    const __half* vgh = g_vth + (size_t)b * DD * SS;   // [dim][key]
    const int* mrow0 = mask + (size_t)(b * SS + qg0 + r0) * SS;
    const int* mrow1 = mask + (size_t)(b * SS + qg0 + r1) * SS;

    // ---- issue K0 + V0 cp.async immediately (no aliasing anywhere) ----
    {
        __half* hk0 = (__half*)(sm + KS0_OFF);
        __half* hv0 = (__half*)(sm + VT0_OFF);
        #pragma unroll
        for (int l = 0; l < 2; l++) {
            int i = tid + l * NT;       // 16B chunk index, 0..511
            int row = i >> 3, c = i & 7;
            cpa16((unsigned)__cvta_generic_to_shared(hk0 + row * KH_STRIDE + c * 8),
                  kgh + (size_t)row * DD + c * 8);
            cpa16((unsigned)__cvta_generic_to_shared(hv0 + row * VT_STRIDE + c * 8),
                  vgh + (size_t)row * SS + c * 8);
        }
        CP_COMMIT();
    }

    // ---- stage pos_table as fp16 [j][dim] ----
    {
        const float4* ptg = (const float4*)pt;
        for (int i = tid; i < 129 * 16; i += NT) {
            int j = i >> 4, c4 = i & 15;
            float4 p4 = ptg[i];
            __half2* d = (__half2*)(hpt + j * PT_STRIDE + c4 * 4);
            d[0] = __floats2half2_rn(p4.x, p4.y);
            d[1] = __floats2half2_rn(p4.z, p4.w);
        }
    }

    // ---- Q fragments (fp16 half2 pairs) straight from gmem ----
    unsigned aq[4][4];
    {
        const float* q0 = q + (size_t)(b * SS + qg0 + r0) * DD;
        const float* q1 = q + (size_t)(b * SS + qg0 + r1) * DD;
        #pragma unroll
        for (int s = 0; s < 4; s++) {
            aq[s][0] = packh2(q0[16*s + 2*u],     q0[16*s + 2*u + 1]);
            aq[s][1] = packh2(q1[16*s + 2*u],     q1[16*s + 2*u + 1]);
            aq[s][2] = packh2(q0[16*s + 2*u + 8], q0[16*s + 2*u + 9]);
            aq[s][3] = packh2(q1[16*s + 2*u + 8], q1[16*s + 2*u + 9]);
        }
    }
    __syncthreads();

    // ---- rp table via fp16 MMA, split across key-half warp groups ----
    if (h == 0) rp_mma_chunk<0, 9>(aq, hpt, rp, r0, r1, u, g);
    else        rp_mma_chunk<9, 8>(aq, hpt, rp, r0, r1, u, g);
    __syncthreads();

    const float rpn0 = rp[r0 * RP_STRIDE + 0],   rpn1 = rp[r1 * RP_STRIDE + 0];
    const float rpp0 = rp[r0 * RP_STRIDE + 128], rpp1 = rp[r1 * RP_STRIDE + 128];

    float ps0 = 0.f, ps1 = 0.f;
    float co[8][4];
    #pragma unroll
    for (int j = 0; j < 8; j++) { co[j][0]=0.f; co[j][1]=0.f; co[j][2]=0.f; co[j][3]=0.f; }

    for (int kt = 0; kt < SS / TK; kt++) {
        const int kg0 = kt * TK;
        const int D   = kg0 - qg0;
        const __half* hk = (const __half*)(sm + ((kt & 1) ? KS1_OFF : KS0_OFF));
        const __half* hv = (const __half*)(sm + ((kt & 1) ? VT1_OFF : VT0_OFF));

        // ---- single wait + barrier per tile ----
        CP_WAIT(0);
        __syncthreads();

        // ---- issue next tile's K/V cp.async into the other buffers ----
        if (kt < 15) {
            __half* hkn = (__half*)(sm + (((kt + 1) & 1) ? KS1_OFF : KS0_OFF));
            __half* hvn = (__half*)(sm + (((kt + 1) & 1) ? VT1_OFF : VT0_OFF));
            #pragma unroll
            for (int l = 0; l < 2; l++) {
                int i = tid + l * NT;
                int row = i >> 3, c = i & 7;
                cpa16((unsigned)__cvta_generic_to_shared(hkn + row * KH_STRIDE + c * 8),
                      kgh + (size_t)(kg0 + TK + row) * DD + c * 8);
                cpa16((unsigned)__cvta_generic_to_shared(hvn + row * VT_STRIDE + c * 8),
                      vgh + (size_t)row * SS + (kg0 + TK) + c * 8);
            }
            CP_COMMIT();
        }

        // ---- mask LDGs for this warp's key half ----
        int4 ma0, ma1, mb0, mb1;
        {
            const int4* p0 = (const int4*)(mrow0 + kg0 + 32 * h) + 2 * u;
            const int4* p1 = (const int4*)(mrow1 + kg0 + 32 * h) + 2 * u;
            ma0 = p0[0]; ma1 = p0[1];
            mb0 = p1[0]; mb1 = p1[1];
        }

        // ---- QK^T: 16 fp16 MMAs (4 key blocks x 4 k-slices) ----
        float c[4][4];
        #pragma unroll
        for (int jl = 0; jl < 4; jl++) { c[jl][0]=0.f; c[jl][1]=0.f; c[jl][2]=0.f; c[jl][3]=0.f; }
        #pragma unroll
        for (int s = 0; s < 4; s++) {
            #pragma unroll
            for (int jl = 0; jl < 4; jl++) {
                int key = 32*h + 8*jl + g;
                unsigned b0 = *(const unsigned*)(hk + key * KH_STRIDE + 16*s + 2*u);
                unsigned b1 = *(const unsigned*)(hk + key * KH_STRIDE + 16*s + 2*u + 8);
                mma_f16(c[jl], aq[s], b0, b1);
            }
        }

        // ---- assemble 32-bit mask words for the key half ----
        unsigned mw0, mw1;
        {
            unsigned b0 = pack8(ma0, ma1) << (8 * u);
            unsigned b1 = pack8(mb0, mb1) << (8 * u);
            b0 |= __shfl_xor_sync(0xffffffffu, b0, 1);
            b1 |= __shfl_xor_sync(0xffffffffu, b1, 1);
            b0 |= __shfl_xor_sync(0xffffffffu, b0, 2);
            b1 |= __shfl_xor_sync(0xffffffffu, b1, 2);
            mw0 = b0; mw1 = b1;
        }

        // ---- epilogue: p = exp(dot*0.125 + rp')   [rp' has -4 folded in] ----
        const bool nearT = (D >= -64) && (D <= 64);
        #pragma unroll
        for (int jl = 0; jl < 4; jl++) {
            const int lc0 = 8*jl + 2*u, lc1 = lc0 + 1;       // local bit index
            const int col0 = 32*h + lc0, col1 = col0 + 1;    // key in tile
            float rv00, rv01, rv10, rv11;
            if (nearT) {
                int i00 = min(max(D + col0 - r0, -64), 64) + 64;
                int i01 = min(max(D + col1 - r0, -64), 64) + 64;
                int i10 = min(max(D + col0 - r1, -64), 64) + 64;
                int i11 = min(max(D + col1 - r1, -64), 64) + 64;
                rv00 = rp[r0 * RP_STRIDE + i00]; rv01 = rp[r0 * RP_STRIDE + i01];
                rv10 = rp[r1 * RP_STRIDE + i10]; rv11 = rp[r1 * RP_STRIDE + i11];
            } else if (D > 0) {
                rv00 = rpp0; rv01 = rpp0; rv10 = rpp1; rv11 = rpp1;
            } else {
                rv00 = rpn0; rv01 = rpn0; rv10 = rpn1; rv11 = rpn1;
            }
            float p00 = ((mw0 >> lc0) & 1) ? 0.f : __expf(fmaf(c[jl][0], 0.125f, rv00));
            float p01 = ((mw0 >> lc1) & 1) ? 0.f : __expf(fmaf(c[jl][1], 0.125f, rv01));
            float p10 = ((mw1 >> lc0) & 1) ? 0.f : __expf(fmaf(c[jl][2], 0.125f, rv10));
            float p11 = ((mw1 >> lc1) & 1) ? 0.f : __expf(fmaf(c[jl][3], 0.125f, rv11));
            ps0 += p00 + p01;
            ps1 += p10 + p11;
            c[jl][0] = p00; c[jl][1] = p01; c[jl][2] = p10; c[jl][3] = p11;
        }

        // ---- PV: 16 fp16 MMAs; A packs straight from P (no permutation) ----
        #pragma unroll
        for (int sl = 0; sl < 2; sl++) {
            unsigned a[4] = {
                packh2(c[2*sl][0],   c[2*sl][1]),
                packh2(c[2*sl][2],   c[2*sl][3]),
                packh2(c[2*sl+1][0], c[2*sl+1][1]),
                packh2(c[2*sl+1][2], c[2*sl+1][3]) };
            #pragma unroll
            for (int j = 0; j < 8; j++) {
                int dim = 8*j + g;
                unsigned b0 = *(const unsigned*)(hv + dim * VT_STRIDE + 32*h + 16*sl + 2*u);
                unsigned b1 = *(const unsigned*)(hv + dim * VT_STRIDE + 32*h + 16*sl + 2*u + 8);
                mma_f16(co[j], a, b0, b1);
            }
        }
    }

    // ---- quad reduction of partial denominators ----
    ps0 += __shfl_xor_sync(0xffffffffu, ps0, 1);
    ps0 += __shfl_xor_sync(0xffffffffu, ps0, 2);
    ps1 += __shfl_xor_sync(0xffffffffu, ps1, 1);
    ps1 += __shfl_xor_sync(0xffffffffu, ps1, 2);

    // ---- cross-half reduction via smem (reuses dead rp region) ----
    float* red   = sm + RP_OFF;
    float* psred = red + 64 * RED_STRIDE;
    __syncthreads();
    if (h == 1) {
        #pragma unroll
        for (int j = 0; j < 8; j++) {
            int col = 8*j + 2*u;
            red[r0 * RED_STRIDE + col]     = co[j][0];
            red[r0 * RED_STRIDE + col + 1] = co[j][1];
            red[r1 * RED_STRIDE + col]     = co[j][2];
            red[r1 * RED_STRIDE + col + 1] = co[j][3];
        }
        if (u == 0) { psred[r0] = ps0; psred[r1] = ps1; }
    }
    __syncthreads();
    if (h == 0) {
        const float il0 = 1.0f / (ps0 + psred[r0]);
        const float il1 = 1.0f / (ps1 + psred[r1]);
        float* o0 = out + (size_t)(b * SS + qg0 + r0) * DD;
        float* o1 = out + (size_t)(b * SS + qg0 + r1) * DD;
        #pragma unroll
        for (int j = 0; j < 8; j++) {
            int col = 8*j + 2*u;
            float2 v0, v1;
            v0.x = (co[j][0] + red[r0 * RED_STRIDE + col])     * il0;
            v0.y = (co[j][1] + red[r0 * RED_STRIDE + col + 1]) * il0;
            v1.x = (co[j][2] + red[r1 * RED_STRIDE + col])     * il1;
            v1.y = (co[j][3] + red[r1 * RED_STRIDE + col + 1]) * il1;
            *(float2*)(o0 + col) = v0;
            *(float2*)(o1 + col) = v1;
        }
    }
}

extern "C" void kernel_launch(void* const* d_in, const int* in_sizes, int n_in,
                              void* d_out, int out_size) {
    const float* q    = (const float*)d_in[0];
    const float* k    = (const float*)d_in[1];
    const float* v    = (const float*)d_in[2];
    const int*   mask = (const int*)d_in[3];
    const float* pt   = (const float*)d_in[4];
    float*       out  = (float*)d_out;

    cvt_k_kernel<<<(TOTAL_ELEMS / 4) / 256, 256>>>((const float4*)k);
    cvt_vt_kernel<<<BB * 16, 256>>>((const float4*)v);

    size_t smem = SMEM_FLOATS * sizeof(float);
    cudaFuncSetAttribute(attn_tc_kernel,
                         cudaFuncAttributeMaxDynamicSharedMemorySize, (int)smem);
    dim3 grid(SS / TQ, BB);
    attn_tc_kernel<<<grid, NT, smem>>>(q, mask, pt, out);
}